// round 7
// baseline (speedup 1.0000x reference)
#include <cuda_runtime.h>
#include <cuda_bf16.h>
#include <cstdint>

// Problem: B=128, N=128, D=1024, H=8, HD=128, M = B*N = 16384
#define PLANE  (16384ull * 1024ull)     // activation plane elems (bf16)
#define WPLANE (1024ull * 1024ull)      // weight plane elems (bf16)
// layout: inh(3) inl(3) ohb(7) olb(7) ath atl | whb(8) wlb(8)
__device__ __align__(1024) __nv_bfloat16 g_bf[22ull * PLANE + 16ull * WPLANE];

typedef __nv_bfloat16 bf16;

// ======================= PTX helpers =========================================
__device__ __forceinline__ uint32_t s2u(const void* p) {
    uint32_t a;
    asm("{ .reg .u64 t; cvta.to.shared.u64 t, %1; cvt.u32.u64 %0, t; }"
        : "=r"(a) : "l"(p));
    return a;
}
__device__ __forceinline__ void ldsm4(uint32_t* r, uint32_t addr) {
    asm volatile("ldmatrix.sync.aligned.m8n8.x4.shared.b16 {%0,%1,%2,%3}, [%4];"
                 : "=r"(r[0]), "=r"(r[1]), "=r"(r[2]), "=r"(r[3]) : "r"(addr));
}
__device__ __forceinline__ void ldsm4t(uint32_t* r, uint32_t addr) {
    asm volatile("ldmatrix.sync.aligned.m8n8.x4.trans.shared.b16 {%0,%1,%2,%3}, [%4];"
                 : "=r"(r[0]), "=r"(r[1]), "=r"(r[2]), "=r"(r[3]) : "r"(addr));
}
__device__ __forceinline__ void mma_bf16(float* d, const uint32_t* a, const uint32_t* b) {
    asm volatile(
        "mma.sync.aligned.m16n8k16.row.col.f32.bf16.bf16.f32 "
        "{%0,%1,%2,%3},{%4,%5,%6,%7},{%8,%9},{%0,%1,%2,%3};"
        : "+f"(d[0]), "+f"(d[1]), "+f"(d[2]), "+f"(d[3])
        : "r"(a[0]), "r"(a[1]), "r"(a[2]), "r"(a[3]), "r"(b[0]), "r"(b[1]));
}
#define CP16(dst, src) \
    asm volatile("cp.async.cg.shared.global [%0], [%1], 16;" :: "r"(dst), "l"(src))
#define CPCOMMIT() asm volatile("cp.async.commit_group;" ::: "memory")
#define CPWAIT2()  asm volatile("cp.async.wait_group 2;" ::: "memory")
#define CPWAIT1()  asm volatile("cp.async.wait_group 1;" ::: "memory")
#define CPWAIT0()  asm volatile("cp.async.wait_group 0;" ::: "memory")

__device__ __forceinline__ void split1(float v, bf16& h, bf16& l) {
    h = __float2bfloat16(v);
    l = __float2bfloat16(v - __bfloat162float(h));
}
__device__ __forceinline__ void packsplit2(float x0, float x1,
                                           uint32_t& hi, uint32_t& lo) {
    bf16 h0, l0, h1, l1;
    split1(x0, h0, l0); split1(x1, h1, l1);
    __nv_bfloat162 hh; hh.x = h0; hh.y = h1;
    __nv_bfloat162 ll; ll.x = l0; ll.y = l1;
    hi = *(uint32_t*)&hh; lo = *(uint32_t*)&ll;
}

// ======================= fused input split (3 inputs) ========================
__global__ __launch_bounds__(256) void split_all(
    const float* __restrict__ s0, const float* __restrict__ s1,
    const float* __restrict__ s2, bf16* __restrict__ hb, bf16* __restrict__ lb)
{
    const float* src = (blockIdx.y == 0) ? s0 : (blockIdx.y == 1) ? s1 : s2;
    bf16* h = hb + (size_t)blockIdx.y * PLANE;
    bf16* l = lb + (size_t)blockIdx.y * PLANE;
    size_t i4 = ((size_t)blockIdx.x * 256 + threadIdx.x) * 4;
    float4 v = *(const float4*)(src + i4);
    uint32_t hh0, ll0, hh1, ll1;
    packsplit2(v.x, v.y, hh0, ll0);
    packsplit2(v.z, v.w, hh1, ll1);
    *(uint32_t*)(h + i4)     = hh0; *(uint32_t*)(h + i4 + 2) = hh1;
    *(uint32_t*)(l + i4)     = ll0; *(uint32_t*)(l + i4 + 2) = ll1;
}

// ======================= fused weight transpose + split (4 weights) ==========
__global__ __launch_bounds__(256) void transpose4(
    const float* __restrict__ s0, const float* __restrict__ s1,
    const float* __restrict__ s2, const float* __restrict__ s3,
    bf16* __restrict__ hb, bf16* __restrict__ lb)
{
    const float* src = (blockIdx.z == 0) ? s0 : (blockIdx.z == 1) ? s1
                     : (blockIdx.z == 2) ? s2 : s3;
    bf16* h = hb + (size_t)blockIdx.z * WPLANE;
    bf16* l = lb + (size_t)blockIdx.z * WPLANE;
    __shared__ float t[32][33];
    int bx = blockIdx.x * 32, by = blockIdx.y * 32;
    int tx = threadIdx.x, ty = threadIdx.y;
#pragma unroll
    for (int i = ty; i < 32; i += 8)
        t[i][tx] = src[(size_t)(by + i) * 1024 + bx + tx];
    __syncthreads();
#pragma unroll
    for (int i = ty; i < 32; i += 8) {
        bf16 hh, ll;
        split1(t[tx][i], hh, ll);
        size_t o = (size_t)(bx + i) * 1024 + by + tx;
        h[o] = hh; l[o] = ll;
    }
}

// ======================= bf16-split mma.sync GEMM ============================
// 512 threads, CTA tile 128x128, warp grid 4x4 (warp tile 32x32).
// Register double-buffered fragments: MMAs of chunk c use frags loaded during
// chunk c-1 -> zero smem dependency inside the MMA stream. 1 barrier/chunk.
// Stage layout (bytes): Ah@0 Al@6144 Bh@12288 Bl@18432, stage stride 24576.
#define GEMM_SMEM (4 * 24576)

struct Frag {
    uint32_t ah[2][4], al[2][4];
    uint32_t bh[4][2], bl[4][2];
};

__device__ __forceinline__ void ldfrag(Frag& f, uint32_t off,
                                       int wm, int wn,
                                       uint32_t aLane, uint32_t bLane)
{
    ldsm4(f.ah[0], off + (uint32_t)((wm * 32) * 48) + aLane);
    ldsm4(f.ah[1], off + (uint32_t)((wm * 32 + 16) * 48) + aLane);
    ldsm4(f.al[0], off + 6144u + (uint32_t)((wm * 32) * 48) + aLane);
    ldsm4(f.al[1], off + 6144u + (uint32_t)((wm * 32 + 16) * 48) + aLane);
    uint32_t q[4];
    ldsm4(q, off + 12288u + (uint32_t)((wn * 32) * 48) + bLane);
    f.bh[0][0] = q[0]; f.bh[0][1] = q[1]; f.bh[1][0] = q[2]; f.bh[1][1] = q[3];
    ldsm4(q, off + 12288u + (uint32_t)((wn * 32 + 16) * 48) + bLane);
    f.bh[2][0] = q[0]; f.bh[2][1] = q[1]; f.bh[3][0] = q[2]; f.bh[3][1] = q[3];
    ldsm4(q, off + 18432u + (uint32_t)((wn * 32) * 48) + bLane);
    f.bl[0][0] = q[0]; f.bl[0][1] = q[1]; f.bl[1][0] = q[2]; f.bl[1][1] = q[3];
    ldsm4(q, off + 18432u + (uint32_t)((wn * 32 + 16) * 48) + bLane);
    f.bl[2][0] = q[0]; f.bl[2][1] = q[1]; f.bl[3][0] = q[2]; f.bl[3][1] = q[3];
}

__global__ __launch_bounds__(512, 1) void gemm_bf(
    const bf16* __restrict__ Ah, const bf16* __restrict__ Al,
    const bf16* __restrict__ Bh, const bf16* __restrict__ Bl,
    float* __restrict__ Cf, bf16* __restrict__ Ch, bf16* __restrict__ Cl,
    const float* __restrict__ bias, int ACB, int ARI, int CCB, int CRI)
{
    extern __shared__ __align__(1024) char smem[];
    const uint32_t sb = s2u(smem);
    const int tid = threadIdx.x;
    const int lane = tid & 31, wid = tid >> 5;
    const int rt = blockIdx.y, ct = blockIdx.x;
    const int bp = ct >> 3, bct = ct & 7;
    const int wm = wid & 3, wn = wid >> 2;
    const int s8 = lane >> 3, r8 = lane & 7;
    const uint32_t aLane = (uint32_t)(((s8 & 1) * 8 + r8) * 48 + (s8 >> 1) * 16);
    const uint32_t bLane = (uint32_t)(((s8 >> 1) * 8 + r8) * 48 + (s8 & 1) * 16);

    // loader mapping: warps 0-7 load A planes, warps 8-15 load B planes
    const int lplane = tid >> 8;                 // 0: A, 1: B
    const int lrow = (tid & 255) >> 1, lhalf = tid & 1;
    const size_t aoff = (size_t)rt * 131072 + (size_t)lrow * ARI + lhalf * 8;
    const size_t boff = (size_t)bp * WPLANE + (size_t)(bct * 128 + lrow) * 1024 + lhalf * 8;
    const uint32_t dstoff = (uint32_t)(lrow * 48 + lhalf * 16);

    float acc[2][4][4];
#pragma unroll
    for (int i = 0; i < 2; i++)
#pragma unroll
        for (int j = 0; j < 4; j++)
#pragma unroll
            for (int k = 0; k < 4; k++) acc[i][j][k] = 0.f;

    auto load_chunk = [&](int c) {
        const int kk = c * 16;
        const uint32_t st = sb + (uint32_t)((c & 3) * 24576) + dstoff;
        if (lplane == 0) {
            const size_t a = aoff + (size_t)(kk >> 7) * ACB + (kk & 127);
            CP16(st,        Ah + a);
            CP16(st + 6144, Al + a);
        } else {
            const size_t b = boff + kk;
            CP16(st + 12288, Bh + b);
            CP16(st + 18432, Bl + b);
        }
    };

    load_chunk(0); CPCOMMIT();
    load_chunk(1); CPCOMMIT();
    load_chunk(2); CPCOMMIT();

    Frag f0, f1;
    CPWAIT2();
    __syncthreads();
    ldfrag(f0, sb, wm, wn, aLane, bLane);

    auto step = [&](int c, Frag& cur, Frag& nxt) {
        CPWAIT1();               // chunk c+1 resident
        __syncthreads();         // visible to all; also fences stage reuse
        if (c + 1 < 64)
            ldfrag(nxt, sb + (uint32_t)(((c + 1) & 3) * 24576), wm, wn, aLane, bLane);
        // MMAs: zero smem dependency (fragments loaded last iteration)
#pragma unroll
        for (int mt = 0; mt < 2; mt++)
#pragma unroll
            for (int nt = 0; nt < 4; nt++)
                mma_bf16(acc[mt][nt], cur.ah[mt], cur.bh[nt]);
#pragma unroll
        for (int mt = 0; mt < 2; mt++)
#pragma unroll
            for (int nt = 0; nt < 4; nt++)
                mma_bf16(acc[mt][nt], cur.ah[mt], cur.bl[nt]);
#pragma unroll
        for (int mt = 0; mt < 2; mt++)
#pragma unroll
            for (int nt = 0; nt < 4; nt++)
                mma_bf16(acc[mt][nt], cur.al[mt], cur.bh[nt]);
        if (c + 3 < 64) load_chunk(c + 3);
        CPCOMMIT();
    };

    for (int c = 0; c < 64; c += 2) {
        step(c, f0, f1);
        step(c + 1, f1, f0);
    }

    // ---- epilogue ----
    const int g = lane >> 2, cp2 = (lane & 3) * 2;
    const size_t cbase = (size_t)bp * PLANE + (size_t)rt * 131072 + (size_t)bct * CCB;
#pragma unroll
    for (int mt = 0; mt < 2; mt++) {
#pragma unroll
        for (int nt = 0; nt < 4; nt++) {
            int r0 = wm * 32 + mt * 16 + g;
            int col = wn * 32 + nt * 8 + cp2;
            float v0 = acc[mt][nt][0], v1 = acc[mt][nt][1];
            float v2 = acc[mt][nt][2], v3 = acc[mt][nt][3];
            size_t o0 = cbase + (size_t)r0 * CRI + col;
            size_t o1 = cbase + (size_t)(r0 + 8) * CRI + col;
            if (Cf) {
                float b0 = bias[ct * 128 + col], b1 = bias[ct * 128 + col + 1];
                *(float2*)(Cf + o0) = make_float2(v0 + b0, v1 + b1);
                *(float2*)(Cf + o1) = make_float2(v2 + b0, v3 + b1);
            } else {
                uint32_t hh, ll;
                packsplit2(v0, v1, hh, ll);
                *(uint32_t*)(Ch + o0) = hh; *(uint32_t*)(Cl + o0) = ll;
                packsplit2(v2, v3, hh, ll);
                *(uint32_t*)(Ch + o1) = hh; *(uint32_t*)(Cl + o1) = ll;
            }
        }
    }
}

// ======================= mma attention (register-resident P) =================
// One CTA per (b,h). Warp w owns rows w*16..w*16+15 (full 128 cols).
// smem: Q stages@0 (4 x 12288: h@0 l@6144), K/V stages@49152 (4 x 8704).
#define ATT_SMEM 83968
#define ATT_KST  49152u

__global__ __launch_bounds__(256, 1) void attn_mma(
    const bf16* __restrict__ ohb, const bf16* __restrict__ olb,
    bf16* __restrict__ ath, bf16* __restrict__ atl)
{
    extern __shared__ __align__(1024) char smem[];
    const uint32_t sb = s2u(smem);
    const int tid = threadIdx.x;
    const int lane = tid & 31, w = tid >> 5;
    const size_t bhoff = (size_t)blockIdx.x * 16384;

    // plane order in ohb: 0 qw, 1 kw, 2 vw, 3 qp, 4 kp, 5 qc, 6 kc
    const int qpl[3] = { 0, 3, 5 }, kpl[3] = { 1, 4, 6 };

    const int s8 = lane >> 3, r8 = lane & 7;
    const uint32_t aLane = (uint32_t)(((s8 & 1) * 8 + r8) * 48 + (s8 >> 1) * 16);
    const uint32_t kr = (uint32_t)(lane & 15);
    const uint32_t nf = (uint32_t)((lane >> 4) * 8);
    const uint32_t wrow48 = (uint32_t)(w * 16 * 48);

    const int qrow = tid >> 1, qhalf = tid & 1;
    const uint32_t qdst = (uint32_t)(qrow * 48 + qhalf * 16);
    const int krow = tid >> 4, kseg = tid & 15;
    const uint32_t kdst = (uint32_t)(krow * 272 + kseg * 16);

    auto loadQK = [&](int it) {
        int s = it >> 3, c = it & 7;
        uint32_t qs = sb + (uint32_t)((it & 3) * 12288) + qdst;
        size_t qsrc = (size_t)qpl[s] * PLANE + bhoff + (size_t)qrow * 128 + c * 16 + qhalf * 8;
        CP16(qs,        ohb + qsrc);
        CP16(qs + 6144, olb + qsrc);
        uint32_t ks = sb + ATT_KST + (uint32_t)((it & 3) * 8704) + kdst;
        size_t ksrc = (size_t)kpl[s] * PLANE + bhoff + (size_t)(c * 16 + krow) * 128 + kseg * 8;
        CP16(ks,        ohb + ksrc);
        CP16(ks + 4352, olb + ksrc);
    };
    auto loadV = [&](int v) {
        uint32_t ks = sb + ATT_KST + (uint32_t)((v & 3) * 8704) + kdst;
        size_t ksrc = 2ull * PLANE + bhoff + (size_t)(v * 16 + krow) * 128 + kseg * 8;
        CP16(ks,        ohb + ksrc);
        CP16(ks + 4352, olb + ksrc);
    };

    float acc[16][4];
#pragma unroll
    for (int i = 0; i < 16; i++)
#pragma unroll
        for (int j = 0; j < 4; j++) acc[i][j] = 0.f;

    loadQK(0); CPCOMMIT();
    loadQK(1); CPCOMMIT();
    loadQK(2); CPCOMMIT();

    // ---- Phase 1: sim (24 iters = 3 streams x 8 k-chunks) ----
    for (int it = 0; it < 24; it++) {
        CPWAIT2();
        __syncthreads();
        if (it + 3 < 24) loadQK(it + 3);
        CPCOMMIT();

        const uint32_t qs = sb + (uint32_t)((it & 3) * 12288);
        const uint32_t ks = sb + ATT_KST + (uint32_t)((it & 3) * 8704);
        uint32_t ah[4], al[4];
        ldsm4(ah, qs + wrow48 + aLane);
        ldsm4(al, qs + 6144 + wrow48 + aLane);
#pragma unroll
        for (int gp = 0; gp < 4; gp++) {
            uint32_t b0h[4], b0l[4], b1h[4], b1l[4];
            uint32_t a0 = ks + kr * 272 + ((2 * gp) * 16 + nf) * 2;
            uint32_t a1 = ks + kr * 272 + ((2 * gp + 1) * 16 + nf) * 2;
            ldsm4t(b0h, a0); ldsm4t(b0l, a0 + 4352);
            ldsm4t(b1h, a1); ldsm4t(b1l, a1 + 4352);
            float* c0 = acc[4 * gp],     *c1 = acc[4 * gp + 1];
            float* c2 = acc[4 * gp + 2], *c3 = acc[4 * gp + 3];
            mma_bf16(c0, ah, b0h);     mma_bf16(c1, ah, b0h + 2);
            mma_bf16(c2, ah, b1h);     mma_bf16(c3, ah, b1h + 2);
            mma_bf16(c0, al, b0h);     mma_bf16(c1, al, b0h + 2);
            mma_bf16(c2, al, b1h);     mma_bf16(c3, al, b1h + 2);
            mma_bf16(c0, ah, b0l);     mma_bf16(c1, ah, b0l + 2);
            mma_bf16(c2, ah, b1l);     mma_bf16(c3, ah, b1l + 2);
        }
    }

    // drain QK traffic, then prefetch V into stages 0..2 (overlaps softmax)
    CPWAIT0();
    __syncthreads();
    loadV(0); CPCOMMIT();
    loadV(1); CPCOMMIT();
    loadV(2); CPCOMMIT();

    // ---- Phase 2: softmax (warp-local; lane rows g and g+8) ----
    const float SC = 0.08838834764831845f;   // 128^-0.5
    float m0 = -1e30f, m1 = -1e30f;
#pragma unroll
    for (int nt = 0; nt < 16; nt++) {
#pragma unroll
        for (int j = 0; j < 4; j++) acc[nt][j] *= SC;
        m0 = fmaxf(m0, fmaxf(acc[nt][0], acc[nt][1]));
        m1 = fmaxf(m1, fmaxf(acc[nt][2], acc[nt][3]));
    }
    m0 = fmaxf(m0, __shfl_xor_sync(0xffffffffu, m0, 1));
    m0 = fmaxf(m0, __shfl_xor_sync(0xffffffffu, m0, 2));
    m1 = fmaxf(m1, __shfl_xor_sync(0xffffffffu, m1, 1));
    m1 = fmaxf(m1, __shfl_xor_sync(0xffffffffu, m1, 2));
    float sum0 = 0.f, sum1 = 0.f;
#pragma unroll
    for (int nt = 0; nt < 16; nt++) {
        acc[nt][0] = __expf(acc[nt][0] - m0); sum0 += acc[nt][0];
        acc[nt][1] = __expf(acc[nt][1] - m0); sum0 += acc[nt][1];
        acc[nt][2] = __expf(acc[nt][2] - m1); sum1 += acc[nt][2];
        acc[nt][3] = __expf(acc[nt][3] - m1); sum1 += acc[nt][3];
    }
    sum0 += __shfl_xor_sync(0xffffffffu, sum0, 1);
    sum0 += __shfl_xor_sync(0xffffffffu, sum0, 2);
    sum1 += __shfl_xor_sync(0xffffffffu, sum1, 1);
    sum1 += __shfl_xor_sync(0xffffffffu, sum1, 2);
    const float inv0 = 1.f / sum0, inv1 = 1.f / sum1;

    // ---- repack P into A-fragments (C-frag layout == A-frag layout) ----
    uint32_t ph[8][4], pl[8][4];
#pragma unroll
    for (int c = 0; c < 8; c++) {
        packsplit2(acc[2*c][0]   * inv0, acc[2*c][1]   * inv0, ph[c][0], pl[c][0]);
        packsplit2(acc[2*c][2]   * inv1, acc[2*c][3]   * inv1, ph[c][1], pl[c][1]);
        packsplit2(acc[2*c+1][0] * inv0, acc[2*c+1][1] * inv0, ph[c][2], pl[c][2]);
        packsplit2(acc[2*c+1][2] * inv1, acc[2*c+1][3] * inv1, ph[c][3], pl[c][3]);
    }
#pragma unroll
    for (int i = 0; i < 16; i++)
#pragma unroll
        for (int j = 0; j < 4; j++) acc[i][j] = 0.f;

    // ---- Phase 3: out = P * V (8 k-chunks) ----
    for (int v = 0; v < 8; v++) {
        CPWAIT2();
        __syncthreads();
        if (v + 3 < 8) loadV(v + 3);
        CPCOMMIT();

        const uint32_t ks = sb + ATT_KST + (uint32_t)((v & 3) * 8704);
#pragma unroll
        for (int gp = 0; gp < 4; gp++) {
            uint32_t b0h[4], b0l[4], b1h[4], b1l[4];
            uint32_t a0 = ks + kr * 272 + ((2 * gp) * 16 + nf) * 2;
            uint32_t a1 = ks + kr * 272 + ((2 * gp + 1) * 16 + nf) * 2;
            ldsm4t(b0h, a0); ldsm4t(b0l, a0 + 4352);
            ldsm4t(b1h, a1); ldsm4t(b1l, a1 + 4352);
            float* c0 = acc[4 * gp],     *c1 = acc[4 * gp + 1];
            float* c2 = acc[4 * gp + 2], *c3 = acc[4 * gp + 3];
            mma_bf16(c0, ph[v], b0h);  mma_bf16(c1, ph[v], b0h + 2);
            mma_bf16(c2, ph[v], b1h);  mma_bf16(c3, ph[v], b1h + 2);
            mma_bf16(c0, pl[v], b0h);  mma_bf16(c1, pl[v], b0h + 2);
            mma_bf16(c2, pl[v], b1h);  mma_bf16(c3, pl[v], b1h + 2);
            mma_bf16(c0, ph[v], b0l);  mma_bf16(c1, ph[v], b0l + 2);
            mma_bf16(c2, ph[v], b1l);  mma_bf16(c3, ph[v], b1l + 2);
        }
    }

    // ---- write att hi/lo planes ----
    {
        const int g = lane >> 2, c2 = (lane & 3) * 2;
        const size_t r0 = bhoff + (size_t)(w * 16 + g) * 128;
#pragma unroll
        for (int nt = 0; nt < 16; nt++) {
            int col = nt * 8 + c2;
            uint32_t hh, ll;
            packsplit2(acc[nt][0], acc[nt][1], hh, ll);
            *(uint32_t*)(ath + r0 + col) = hh;
            *(uint32_t*)(atl + r0 + col) = ll;
            packsplit2(acc[nt][2], acc[nt][3], hh, ll);
            *(uint32_t*)(ath + r0 + 8 * 128 + col) = hh;
            *(uint32_t*)(atl + r0 + 8 * 128 + col) = ll;
        }
    }
}

// ======================= launch ==============================================
extern "C" void kernel_launch(void* const* d_in, const int* in_sizes, int n_in,
                              void* d_out, int out_size)
{
    (void)in_sizes; (void)n_in; (void)out_size;
    const float* inp[3] = { (const float*)d_in[0], (const float*)d_in[1],
                            (const float*)d_in[2] };
    const float* W[8] = { (const float*)d_in[3], (const float*)d_in[4],
                          (const float*)d_in[5], (const float*)d_in[6],
                          (const float*)d_in[7], (const float*)d_in[8],
                          (const float*)d_in[9], (const float*)d_in[10] };
    const float* bo = (const float*)d_in[11];
    float* out = (float*)d_out;

    void* symp = nullptr;
    cudaGetSymbolAddress(&symp, g_bf);
    bf16* P = (bf16*)symp;
    bf16* inh = P;                      // 3 planes
    bf16* inl = P + 3ull * PLANE;       // 3 planes
    bf16* ohb = P + 6ull * PLANE;       // 7 planes: qw kw vw qp kp qc kc
    bf16* olb = P + 13ull * PLANE;      // 7 planes
    bf16* ath = P + 20ull * PLANE;
    bf16* atl = P + 21ull * PLANE;
    bf16* whb = P + 22ull * PLANE;      // 8 weight h planes
    bf16* wlb = whb + 8ull * WPLANE;    // 8 weight l planes

    cudaFuncSetAttribute(gemm_bf, cudaFuncAttributeMaxDynamicSharedMemorySize, GEMM_SMEM);
    cudaFuncSetAttribute(attn_mma, cudaFuncAttributeMaxDynamicSharedMemorySize, ATT_SMEM);

    // 0) split inputs (one launch)
    split_all<<<dim3(16384, 3), 256>>>(inp[0], inp[1], inp[2], inh, inl);

    // 1-2) transpose+split weights (two launches of 4)
    dim3 tgrid(32, 32, 4), tblk(32, 8);
    transpose4<<<tgrid, tblk>>>(W[0], W[1], W[2], W[3], whb, wlb);
    transpose4<<<tgrid, tblk>>>(W[4], W[5], W[6], W[7],
                                whb + 4ull * WPLANE, wlb + 4ull * WPLANE);

    // 3-5) combined projections -> hi/lo planes in head layout
    gemm_bf<<<dim3(24, 128), 512, GEMM_SMEM>>>(
        inh, inl, whb, wlb,
        nullptr, ohb, olb, nullptr, 128, 1024, 16384, 128);                 // words: q,k,v
    gemm_bf<<<dim3(16, 128), 512, GEMM_SMEM>>>(
        inh + PLANE, inl + PLANE, whb + 3ull * WPLANE, wlb + 3ull * WPLANE,
        nullptr, ohb + 3ull * PLANE, olb + 3ull * PLANE, nullptr,
        128, 1024, 16384, 128);                                             // position: q,k
    gemm_bf<<<dim3(16, 128), 512, GEMM_SMEM>>>(
        inh + 2ull * PLANE, inl + 2ull * PLANE,
        whb + 5ull * WPLANE, wlb + 5ull * WPLANE,
        nullptr, ohb + 5ull * PLANE, olb + 5ull * PLANE, nullptr,
        128, 1024, 16384, 128);                                             // conscious: q,k

    // 6) attention -> att planes
    attn_mma<<<1024, 256, ATT_SMEM>>>(ohb, olb, ath, atl);

    // 7) final GEMM: att * Wo^T + bias -> f32 out (row-major)
    gemm_bf<<<dim3(8, 128), 512, GEMM_SMEM>>>(
        ath, atl, whb + 7ull * WPLANE, wlb + 7ull * WPLANE,
        out, nullptr, nullptr, bo, 16384, 128, 128, 1024);
}

// round 8
// speedup vs baseline: 1.3999x; 1.3999x over previous
#include <cuda_runtime.h>
#include <cuda_bf16.h>
#include <cstdint>

// Problem: B=128, N=128, D=1024, H=8, HD=128, M = B*N = 16384
#define PLANE    (16384ull * 1024ull)   // activation plane elems
#define WPLANE_F (1024ull * 1024ull)    // f32 weight plane elems
// bf16-unit layout: inf32(3 f32 =6u) ohb(7) olb(7) attf32(1 f32 =2u) | wf32(8 f32 =16u)
__device__ __align__(1024) __nv_bfloat16 g_bf[22ull * PLANE + 16ull * 2ull * WPLANE_F / 2ull + 16ull * WPLANE_F];

typedef __nv_bfloat16 bf16;

// ======================= PTX helpers =========================================
__device__ __forceinline__ uint32_t s2u(const void* p) {
    uint32_t a;
    asm("{ .reg .u64 t; cvta.to.shared.u64 t, %1; cvt.u32.u64 %0, t; }"
        : "=r"(a) : "l"(p));
    return a;
}
__device__ __forceinline__ void ldsm4(uint32_t* r, uint32_t addr) {
    asm volatile("ldmatrix.sync.aligned.m8n8.x4.shared.b16 {%0,%1,%2,%3}, [%4];"
                 : "=r"(r[0]), "=r"(r[1]), "=r"(r[2]), "=r"(r[3]) : "r"(addr));
}
__device__ __forceinline__ void ldsm4t(uint32_t* r, uint32_t addr) {
    asm volatile("ldmatrix.sync.aligned.m8n8.x4.trans.shared.b16 {%0,%1,%2,%3}, [%4];"
                 : "=r"(r[0]), "=r"(r[1]), "=r"(r[2]), "=r"(r[3]) : "r"(addr));
}
__device__ __forceinline__ void mma_bf16(float* d, const uint32_t* a, const uint32_t* b) {
    asm volatile(
        "mma.sync.aligned.m16n8k16.row.col.f32.bf16.bf16.f32 "
        "{%0,%1,%2,%3},{%4,%5,%6,%7},{%8,%9},{%0,%1,%2,%3};"
        : "+f"(d[0]), "+f"(d[1]), "+f"(d[2]), "+f"(d[3])
        : "r"(a[0]), "r"(a[1]), "r"(a[2]), "r"(a[3]), "r"(b[0]), "r"(b[1]));
}
__device__ __forceinline__ void mma_tf32(float* d, const uint32_t* a, const uint32_t* b) {
    asm volatile(
        "mma.sync.aligned.m16n8k8.row.col.f32.tf32.tf32.f32 "
        "{%0,%1,%2,%3},{%4,%5,%6,%7},{%8,%9},{%0,%1,%2,%3};"
        : "+f"(d[0]), "+f"(d[1]), "+f"(d[2]), "+f"(d[3])
        : "r"(a[0]), "r"(a[1]), "r"(a[2]), "r"(a[3]), "r"(b[0]), "r"(b[1]));
}
#define CP16(dst, src) \
    asm volatile("cp.async.cg.shared.global [%0], [%1], 16;" :: "r"(dst), "l"(src))
#define CPCOMMIT() asm volatile("cp.async.commit_group;" ::: "memory")
#define CPWAIT2()  asm volatile("cp.async.wait_group 2;" ::: "memory")
#define CPWAIT0()  asm volatile("cp.async.wait_group 0;" ::: "memory")

__device__ __forceinline__ float tf32r(float x) {   // round-to-nearest tf32
    uint32_t u; asm("cvt.rna.tf32.f32 %0, %1;" : "=r"(u) : "f"(x));
    return __uint_as_float(u);
}
__device__ __forceinline__ void split1(float v, bf16& h, bf16& l) {
    h = __float2bfloat16(v);
    l = __float2bfloat16(v - __bfloat162float(h));
}
__device__ __forceinline__ void packsplit2(float x0, float x1,
                                           uint32_t& hi, uint32_t& lo) {
    bf16 h0, l0, h1, l1;
    split1(x0, h0, l0); split1(x1, h1, l1);
    __nv_bfloat162 hh; hh.x = h0; hh.y = h1;
    __nv_bfloat162 ll; ll.x = l0; ll.y = l1;
    hi = *(uint32_t*)&hh; lo = *(uint32_t*)&ll;
}

// ======================= input rounding (3 inputs -> tf32 f32 planes) ========
__global__ __launch_bounds__(256) void split_all(
    const float* __restrict__ s0, const float* __restrict__ s1,
    const float* __restrict__ s2, float* __restrict__ ob)
{
    const float* src = (blockIdx.y == 0) ? s0 : (blockIdx.y == 1) ? s1 : s2;
    float* o = ob + (size_t)blockIdx.y * PLANE;
    size_t i4 = ((size_t)blockIdx.x * 256 + threadIdx.x) * 4;
    float4 v = *(const float4*)(src + i4);
    v.x = tf32r(v.x); v.y = tf32r(v.y); v.z = tf32r(v.z); v.w = tf32r(v.w);
    *(float4*)(o + i4) = v;
}

// ======================= weight transpose -> tf32 f32 planes (4 each) ========
__global__ __launch_bounds__(256) void transpose4(
    const float* __restrict__ s0, const float* __restrict__ s1,
    const float* __restrict__ s2, const float* __restrict__ s3,
    float* __restrict__ ob)
{
    const float* src = (blockIdx.z == 0) ? s0 : (blockIdx.z == 1) ? s1
                     : (blockIdx.z == 2) ? s2 : s3;
    float* o = ob + (size_t)blockIdx.z * WPLANE_F;
    __shared__ float t[32][33];
    int bx = blockIdx.x * 32, by = blockIdx.y * 32;
    int tx = threadIdx.x, ty = threadIdx.y;
#pragma unroll
    for (int i = ty; i < 32; i += 8)
        t[i][tx] = src[(size_t)(by + i) * 1024 + bx + tx];
    __syncthreads();
#pragma unroll
    for (int i = ty; i < 32; i += 8)
        o[(size_t)(bx + i) * 1024 + by + tx] = tf32r(t[tx][i]);
}

// ======================= single-pass tf32 mma.sync GEMM ======================
// C = A * B^T, A/B pre-rounded tf32 stored as f32. 256 thr, CTA 128x128,
// warp tile 64x32, k16 chunks, 4-stage cp.async ring.
// smem stage: A@0 (128 rows x 80B), B@10240 (128 x 80B); stage stride 20480.
// A idx(r,k) = (r/128)*131072 + (k/128)*ACB + (r%128)*ARI + (k%128)
// C: f32 row-major (final) or bf16 hi/lo head-layout planes (projections).
#define GEMM_SMEM (4 * 20480)

__global__ __launch_bounds__(256, 2) void gemm_tf(
    const float* __restrict__ A, const float* __restrict__ B,
    float* __restrict__ Cf, bf16* __restrict__ Ch, bf16* __restrict__ Cl,
    const float* __restrict__ bias, int ACB, int ARI, int CCB, int CRI)
{
    extern __shared__ __align__(1024) char smem[];
    const uint32_t sb = s2u(smem);
    const int tid = threadIdx.x;
    const int lane = tid & 31, wid = tid >> 5;
    const int rt = blockIdx.y, ct = blockIdx.x;
    const int bp = ct >> 3, bct = ct & 7;
    const int wm = wid & 1, wn = wid >> 1;
    // tf32-frag ldsm lane offsets (f32 tiles viewed as b16 double-width)
    const uint32_t aLane = (uint32_t)((lane & 15) * 80 + (lane >> 4) * 16);
    const uint32_t bLane = (uint32_t)(((lane & 7) + (lane >> 4) * 8) * 80
                                      + ((lane >> 3) & 1) * 16);

    // loader: each thread 4x cp16 per chunk (A p0/p1, B p0/p1)
    const int lrow = tid >> 2, seg = tid & 3;          // row 0-63 (+64 via p)
    const uint32_t dstoff = (uint32_t)(lrow * 80 + seg * 16);

    float acc[4][4][4];
#pragma unroll
    for (int i = 0; i < 4; i++)
#pragma unroll
        for (int j = 0; j < 4; j++)
#pragma unroll
            for (int k = 0; k < 4; k++) acc[i][j][k] = 0.f;

    auto load_chunk = [&](int c) {
        const int kk = c * 16;
        const uint32_t st = sb + (uint32_t)((c & 3) * 20480) + dstoff;
#pragma unroll
        for (int p = 0; p < 2; p++) {
            const int row = lrow + p * 64;
            const size_t asrc = (size_t)rt * 131072 + (size_t)(kk >> 7) * ACB
                              + (size_t)row * ARI + (kk & 127) + seg * 4;
            CP16(st + (uint32_t)(p * 64 * 80), A + asrc);
            const size_t bsrc = (size_t)bp * WPLANE_F
                              + (size_t)(bct * 128 + row) * 1024 + kk + seg * 4;
            CP16(st + 10240u + (uint32_t)(p * 64 * 80), B + bsrc);
        }
    };

    load_chunk(0); CPCOMMIT();
    load_chunk(1); CPCOMMIT();
    load_chunk(2); CPCOMMIT();

    for (int c = 0; c < 64; c++) {
        CPWAIT2();
        __syncthreads();
        if (c + 3 < 64) load_chunk(c + 3);
        CPCOMMIT();

        const uint32_t off = sb + (uint32_t)((c & 3) * 20480);
        // B fragments: both k8 steps, 4 n8-tiles
        uint32_t bt[2][4][2];
#pragma unroll
        for (int ks = 0; ks < 2; ks++)
#pragma unroll
            for (int pr = 0; pr < 2; pr++) {
                uint32_t q[4];
                ldsm4(q, off + 10240u + (uint32_t)((wn * 32 + pr * 16) * 80)
                         + bLane + (uint32_t)(ks * 32));
                bt[ks][2 * pr][0]     = q[0]; bt[ks][2 * pr][1]     = q[1];
                bt[ks][2 * pr + 1][0] = q[2]; bt[ks][2 * pr + 1][1] = q[3];
            }
        // A fragments per k8 step, then 16 MMAs
#pragma unroll
        for (int ks = 0; ks < 2; ks++) {
            uint32_t at[4][4];
#pragma unroll
            for (int mt = 0; mt < 4; mt++)
                ldsm4(at[mt], off + (uint32_t)((wm * 64 + mt * 16) * 80)
                              + aLane + (uint32_t)(ks * 32));
#pragma unroll
            for (int mt = 0; mt < 4; mt++)
#pragma unroll
                for (int nt = 0; nt < 4; nt++)
                    mma_tf32(acc[mt][nt], at[mt], bt[ks][nt]);
        }
    }

    // ---- epilogue ----
    const int g = lane >> 2, cp2 = (lane & 3) * 2;
    const size_t cbase = (size_t)bp * PLANE + (size_t)rt * 131072 + (size_t)bct * CCB;
#pragma unroll
    for (int mt = 0; mt < 4; mt++) {
#pragma unroll
        for (int nt = 0; nt < 4; nt++) {
            int r0 = wm * 64 + mt * 16 + g;
            int col = wn * 32 + nt * 8 + cp2;
            float v0 = acc[mt][nt][0], v1 = acc[mt][nt][1];
            float v2 = acc[mt][nt][2], v3 = acc[mt][nt][3];
            size_t o0 = cbase + (size_t)r0 * CRI + col;
            size_t o1 = cbase + (size_t)(r0 + 8) * CRI + col;
            if (Cf) {
                float b0 = bias[ct * 128 + col], b1 = bias[ct * 128 + col + 1];
                *(float2*)(Cf + o0) = make_float2(v0 + b0, v1 + b1);
                *(float2*)(Cf + o1) = make_float2(v2 + b0, v3 + b1);
            } else {
                uint32_t hh, ll;
                packsplit2(v0, v1, hh, ll);
                *(uint32_t*)(Ch + o0) = hh; *(uint32_t*)(Cl + o0) = ll;
                packsplit2(v2, v3, hh, ll);
                *(uint32_t*)(Ch + o1) = hh; *(uint32_t*)(Cl + o1) = ll;
            }
        }
    }
}

// ======================= mma attention (bf16-split, register-resident P) =====
// One CTA per (b,h). Warp w owns rows w*16..w*16+15 (full 128 cols).
// Output: single f32 plane, tf32-rounded (feeds final tf32 GEMM).
// smem: Q stages@0 (4 x 12288: h@0 l@6144), K/V stages@49152 (4 x 8704).
#define ATT_SMEM 83968
#define ATT_KST  49152u

__global__ __launch_bounds__(256, 1) void attn_mma(
    const bf16* __restrict__ ohb, const bf16* __restrict__ olb,
    float* __restrict__ attf)
{
    extern __shared__ __align__(1024) char smem[];
    const uint32_t sb = s2u(smem);
    const int tid = threadIdx.x;
    const int lane = tid & 31, w = tid >> 5;
    const size_t bhoff = (size_t)blockIdx.x * 16384;

    // plane order in ohb: 0 qw, 1 kw, 2 vw, 3 qp, 4 kp, 5 qc, 6 kc
    const int qpl[3] = { 0, 3, 5 }, kpl[3] = { 1, 4, 6 };

    const int s8 = lane >> 3, r8 = lane & 7;
    const uint32_t aLane = (uint32_t)(((s8 & 1) * 8 + r8) * 48 + (s8 >> 1) * 16);
    const uint32_t kr = (uint32_t)(lane & 15);
    const uint32_t nf = (uint32_t)((lane >> 4) * 8);
    const uint32_t wrow48 = (uint32_t)(w * 16 * 48);

    const int qrow = tid >> 1, qhalf = tid & 1;
    const uint32_t qdst = (uint32_t)(qrow * 48 + qhalf * 16);
    const int krow = tid >> 4, kseg = tid & 15;
    const uint32_t kdst = (uint32_t)(krow * 272 + kseg * 16);

    auto loadQK = [&](int it) {
        int s = it >> 3, c = it & 7;
        uint32_t qs = sb + (uint32_t)((it & 3) * 12288) + qdst;
        size_t qsrc = (size_t)qpl[s] * PLANE + bhoff + (size_t)qrow * 128 + c * 16 + qhalf * 8;
        CP16(qs,        ohb + qsrc);
        CP16(qs + 6144, olb + qsrc);
        uint32_t ks = sb + ATT_KST + (uint32_t)((it & 3) * 8704) + kdst;
        size_t ksrc = (size_t)kpl[s] * PLANE + bhoff + (size_t)(c * 16 + krow) * 128 + kseg * 8;
        CP16(ks,        ohb + ksrc);
        CP16(ks + 4352, olb + ksrc);
    };
    auto loadV = [&](int v) {
        uint32_t ks = sb + ATT_KST + (uint32_t)((v & 3) * 8704) + kdst;
        size_t ksrc = 2ull * PLANE + bhoff + (size_t)(v * 16 + krow) * 128 + kseg * 8;
        CP16(ks,        ohb + ksrc);
        CP16(ks + 4352, olb + ksrc);
    };

    float acc[16][4];
#pragma unroll
    for (int i = 0; i < 16; i++)
#pragma unroll
        for (int j = 0; j < 4; j++) acc[i][j] = 0.f;

    loadQK(0); CPCOMMIT();
    loadQK(1); CPCOMMIT();
    loadQK(2); CPCOMMIT();

    // ---- Phase 1: sim (24 iters = 3 streams x 8 k-chunks) ----
    for (int it = 0; it < 24; it++) {
        CPWAIT2();
        __syncthreads();
        if (it + 3 < 24) loadQK(it + 3);
        CPCOMMIT();

        const uint32_t qs = sb + (uint32_t)((it & 3) * 12288);
        const uint32_t ks = sb + ATT_KST + (uint32_t)((it & 3) * 8704);
        uint32_t ah[4], al[4];
        ldsm4(ah, qs + wrow48 + aLane);
        ldsm4(al, qs + 6144 + wrow48 + aLane);
#pragma unroll
        for (int gp = 0; gp < 4; gp++) {
            uint32_t b0h[4], b0l[4], b1h[4], b1l[4];
            uint32_t a0 = ks + kr * 272 + ((2 * gp) * 16 + nf) * 2;
            uint32_t a1 = ks + kr * 272 + ((2 * gp + 1) * 16 + nf) * 2;
            ldsm4t(b0h, a0); ldsm4t(b0l, a0 + 4352);
            ldsm4t(b1h, a1); ldsm4t(b1l, a1 + 4352);
            float* c0 = acc[4 * gp],     *c1 = acc[4 * gp + 1];
            float* c2 = acc[4 * gp + 2], *c3 = acc[4 * gp + 3];
            mma_bf16(c0, ah, b0h);     mma_bf16(c1, ah, b0h + 2);
            mma_bf16(c2, ah, b1h);     mma_bf16(c3, ah, b1h + 2);
            mma_bf16(c0, al, b0h);     mma_bf16(c1, al, b0h + 2);
            mma_bf16(c2, al, b1h);     mma_bf16(c3, al, b1h + 2);
            mma_bf16(c0, ah, b0l);     mma_bf16(c1, ah, b0l + 2);
            mma_bf16(c2, ah, b1l);     mma_bf16(c3, ah, b1l + 2);
        }
    }

    // drain QK traffic, then prefetch V into stages 0..2 (overlaps softmax)
    CPWAIT0();
    __syncthreads();
    loadV(0); CPCOMMIT();
    loadV(1); CPCOMMIT();
    loadV(2); CPCOMMIT();

    // ---- Phase 2: softmax (warp-local; lane rows g and g+8) ----
    const float SC = 0.08838834764831845f;   // 128^-0.5
    float m0 = -1e30f, m1 = -1e30f;
#pragma unroll
    for (int nt = 0; nt < 16; nt++) {
#pragma unroll
        for (int j = 0; j < 4; j++) acc[nt][j] *= SC;
        m0 = fmaxf(m0, fmaxf(acc[nt][0], acc[nt][1]));
        m1 = fmaxf(m1, fmaxf(acc[nt][2], acc[nt][3]));
    }
    m0 = fmaxf(m0, __shfl_xor_sync(0xffffffffu, m0, 1));
    m0 = fmaxf(m0, __shfl_xor_sync(0xffffffffu, m0, 2));
    m1 = fmaxf(m1, __shfl_xor_sync(0xffffffffu, m1, 1));
    m1 = fmaxf(m1, __shfl_xor_sync(0xffffffffu, m1, 2));
    float sum0 = 0.f, sum1 = 0.f;
#pragma unroll
    for (int nt = 0; nt < 16; nt++) {
        acc[nt][0] = __expf(acc[nt][0] - m0); sum0 += acc[nt][0];
        acc[nt][1] = __expf(acc[nt][1] - m0); sum0 += acc[nt][1];
        acc[nt][2] = __expf(acc[nt][2] - m1); sum1 += acc[nt][2];
        acc[nt][3] = __expf(acc[nt][3] - m1); sum1 += acc[nt][3];
    }
    sum0 += __shfl_xor_sync(0xffffffffu, sum0, 1);
    sum0 += __shfl_xor_sync(0xffffffffu, sum0, 2);
    sum1 += __shfl_xor_sync(0xffffffffu, sum1, 1);
    sum1 += __shfl_xor_sync(0xffffffffu, sum1, 2);
    const float inv0 = 1.f / sum0, inv1 = 1.f / sum1;

    // ---- repack P into A-fragments (C-frag layout == A-frag layout) ----
    uint32_t ph[8][4], pl[8][4];
#pragma unroll
    for (int c = 0; c < 8; c++) {
        packsplit2(acc[2*c][0]   * inv0, acc[2*c][1]   * inv0, ph[c][0], pl[c][0]);
        packsplit2(acc[2*c][2]   * inv1, acc[2*c][3]   * inv1, ph[c][1], pl[c][1]);
        packsplit2(acc[2*c+1][0] * inv0, acc[2*c+1][1] * inv0, ph[c][2], pl[c][2]);
        packsplit2(acc[2*c+1][2] * inv1, acc[2*c+1][3] * inv1, ph[c][3], pl[c][3]);
    }
#pragma unroll
    for (int i = 0; i < 16; i++)
#pragma unroll
        for (int j = 0; j < 4; j++) acc[i][j] = 0.f;

    // ---- Phase 3: out = P * V (8 k-chunks) ----
    for (int v = 0; v < 8; v++) {
        CPWAIT2();
        __syncthreads();
        if (v + 3 < 8) loadV(v + 3);
        CPCOMMIT();

        const uint32_t ks = sb + ATT_KST + (uint32_t)((v & 3) * 8704);
#pragma unroll
        for (int gp = 0; gp < 4; gp++) {
            uint32_t b0h[4], b0l[4], b1h[4], b1l[4];
            uint32_t a0 = ks + kr * 272 + ((2 * gp) * 16 + nf) * 2;
            uint32_t a1 = ks + kr * 272 + ((2 * gp + 1) * 16 + nf) * 2;
            ldsm4t(b0h, a0); ldsm4t(b0l, a0 + 4352);
            ldsm4t(b1h, a1); ldsm4t(b1l, a1 + 4352);
            float* c0 = acc[4 * gp],     *c1 = acc[4 * gp + 1];
            float* c2 = acc[4 * gp + 2], *c3 = acc[4 * gp + 3];
            mma_bf16(c0, ph[v], b0h);  mma_bf16(c1, ph[v], b0h + 2);
            mma_bf16(c2, ph[v], b1h);  mma_bf16(c3, ph[v], b1h + 2);
            mma_bf16(c0, pl[v], b0h);  mma_bf16(c1, pl[v], b0h + 2);
            mma_bf16(c2, pl[v], b1h);  mma_bf16(c3, pl[v], b1h + 2);
            mma_bf16(c0, ph[v], b0l);  mma_bf16(c1, ph[v], b0l + 2);
            mma_bf16(c2, ph[v], b1l);  mma_bf16(c3, ph[v], b1l + 2);
        }
    }

    // ---- write att as tf32-rounded f32 plane ----
    {
        const int g = lane >> 2, c2 = (lane & 3) * 2;
        const size_t r0 = bhoff + (size_t)(w * 16 + g) * 128;
#pragma unroll
        for (int nt = 0; nt < 16; nt++) {
            int col = nt * 8 + c2;
            *(float2*)(attf + r0 + col) =
                make_float2(tf32r(acc[nt][0]), tf32r(acc[nt][1]));
            *(float2*)(attf + r0 + 8 * 128 + col) =
                make_float2(tf32r(acc[nt][2]), tf32r(acc[nt][3]));
        }
    }
}

// ======================= launch ==============================================
extern "C" void kernel_launch(void* const* d_in, const int* in_sizes, int n_in,
                              void* d_out, int out_size)
{
    (void)in_sizes; (void)n_in; (void)out_size;
    const float* inp[3] = { (const float*)d_in[0], (const float*)d_in[1],
                            (const float*)d_in[2] };
    const float* W[8] = { (const float*)d_in[3], (const float*)d_in[4],
                          (const float*)d_in[5], (const float*)d_in[6],
                          (const float*)d_in[7], (const float*)d_in[8],
                          (const float*)d_in[9], (const float*)d_in[10] };
    const float* bo = (const float*)d_in[11];
    float* out = (float*)d_out;

    void* symp = nullptr;
    cudaGetSymbolAddress(&symp, g_bf);
    bf16* P = (bf16*)symp;
    float* inf  = (float*)P;                     // 3 f32 planes (6 bf16 units)
    bf16*  ohb  = P + 6ull * PLANE;              // 7 bf16 hi planes
    bf16*  olb  = P + 13ull * PLANE;             // 7 bf16 lo planes
    float* attf = (float*)(P + 20ull * PLANE);   // 1 f32 plane (2 units)
    float* wf   = (float*)(P + 22ull * PLANE);   // 8 f32 weight planes

    cudaFuncSetAttribute(gemm_tf, cudaFuncAttributeMaxDynamicSharedMemorySize, GEMM_SMEM);
    cudaFuncSetAttribute(attn_mma, cudaFuncAttributeMaxDynamicSharedMemorySize, ATT_SMEM);

    // 0) round inputs to tf32 f32 planes
    split_all<<<dim3(16384, 3), 256>>>(inp[0], inp[1], inp[2], inf);

    // 1-2) transpose weights -> tf32 f32 planes [N][K]
    dim3 tgrid(32, 32, 4), tblk(32, 8);
    transpose4<<<tgrid, tblk>>>(W[0], W[1], W[2], W[3], wf);
    transpose4<<<tgrid, tblk>>>(W[4], W[5], W[6], W[7], wf + 4ull * WPLANE_F);

    // 3-5) combined projections (tf32 single pass) -> bf16 hi/lo head planes
    gemm_tf<<<dim3(24, 128), 256, GEMM_SMEM>>>(
        inf, wf, nullptr, ohb, olb, nullptr, 128, 1024, 16384, 128);        // words: q,k,v
    gemm_tf<<<dim3(16, 128), 256, GEMM_SMEM>>>(
        inf + PLANE, wf + 3ull * WPLANE_F,
        nullptr, ohb + 3ull * PLANE, olb + 3ull * PLANE, nullptr,
        128, 1024, 16384, 128);                                             // position: q,k
    gemm_tf<<<dim3(16, 128), 256, GEMM_SMEM>>>(
        inf + 2ull * PLANE, wf + 5ull * WPLANE_F,
        nullptr, ohb + 5ull * PLANE, olb + 5ull * PLANE, nullptr,
        128, 1024, 16384, 128);                                             // conscious: q,k

    // 6) attention (bf16-split) -> tf32 f32 att plane
    attn_mma<<<1024, 256, ATT_SMEM>>>(ohb, olb, attf);

    // 7) final GEMM: att * Wo^T + bias -> f32 out (row-major)
    gemm_tf<<<dim3(8, 128), 256, GEMM_SMEM>>>(
        attf, wf + 7ull * WPLANE_F,
        out, nullptr, nullptr, bo, 16384, 128, 128, 1024);
}